// round 2
// baseline (speedup 1.0000x reference)
#include <cuda_runtime.h>
#include <cuda_bf16.h>

#define SEQ   512
#define BAT   64
#define DIN   1024
#define DHID  1024
#define DOUT  1024
#define BHD   (BAT*DHID)   // 65536

#define GRID_REC 128       // <= 148 SMs -> all co-resident in wave 1
#define REC_THREADS 256
#define KS_ZR 4            // split-K for z,r GEMMs (2 gates * 16 ntiles * 4 = 128 blocks)
#define KS_N  8            // split-K for n GEMM   (16 ntiles * 8 = 128 blocks)

// ---------------- scratch (device globals; no allocations allowed) ----------
__device__ float g_xz[SEQ*BHD];          // 134 MB each
__device__ float g_xr[SEQ*BHD];
__device__ float g_xn[SEQ*BHD];
__device__ float g_hs[SEQ*BHD];
__device__ float g_h [BHD];
__device__ float g_z [BHD];
__device__ float g_rh[BHD];
__device__ float g_pzr[2*KS_ZR*BHD];     // split-K partials for z,r
__device__ float g_pn [KS_N*BHD];        // split-K partials for n

__device__ unsigned g_barcnt;
__device__ volatile unsigned g_barsense;

// ---------------- init (also resets barrier state each launch) --------------
__global__ void init_h_kernel(const float* __restrict__ h0) {
    int i = blockIdx.x * 256 + threadIdx.x;
    g_h[i] = h0[i];
    if (i == 0) { g_barcnt = 0; g_barsense = 0; }
}

// ---------------- grid barrier (all GRID_REC blocks co-resident) ------------
__device__ __forceinline__ void gbar(unsigned& phase) {
    phase++;
    __threadfence();          // release my writes (gpu scope -> flush/order)
    __syncthreads();
    if (threadIdx.x == 0) {
        unsigned a = atomicAdd(&g_barcnt, 1);
        if (a == GRID_REC - 1) {
            g_barcnt = 0;
            __threadfence();
            g_barsense = phase;
        } else {
            while (g_barsense != phase) { __nanosleep(32); }
        }
    }
    __syncthreads();
    __threadfence();          // acquire: invalidate L1 so fresh peer data is read
}

// ---------------- generic SGEMM: C[M,N] = A[M,K] @ W[N,K]^T + bias ----------
__global__ __launch_bounds__(256)
void sgemm_bias_kernel(const float* __restrict__ A_ext, int a_sel,
                       const float* __restrict__ W, const float* __restrict__ bias,
                       float* __restrict__ C_ext, int c_sel,
                       int M, int N, int K) {
    const float* A = (a_sel == 0) ? A_ext : g_hs;
    float* C = (c_sel == 0) ? g_xz : (c_sel == 1) ? g_xr : (c_sel == 2) ? g_xn : C_ext;

    __shared__ float As[16][68];
    __shared__ float Bs[16][68];

    const int m0 = blockIdx.y * 64;
    const int n0 = blockIdx.x * 64;
    const int tid = threadIdx.x;
    const int row = tid >> 2;          // 0..63
    const int kq  = (tid & 3) * 4;     // 0,4,8,12
    const int ty  = tid >> 4;          // 0..15
    const int tx  = tid & 15;          // 0..15

    float acc[4][4] = {};

    for (int k0 = 0; k0 < K; k0 += 16) {
        float4 av = *(const float4*)&A[(size_t)(m0 + row) * K + k0 + kq];
        float4 wv = *(const float4*)&W[(size_t)(n0 + row) * K + k0 + kq];
        As[kq + 0][row] = av.x; As[kq + 1][row] = av.y;
        As[kq + 2][row] = av.z; As[kq + 3][row] = av.w;
        Bs[kq + 0][row] = wv.x; Bs[kq + 1][row] = wv.y;
        Bs[kq + 2][row] = wv.z; Bs[kq + 3][row] = wv.w;
        __syncthreads();
        #pragma unroll
        for (int kk = 0; kk < 16; ++kk) {
            float4 a4 = *(const float4*)&As[kk][ty * 4];
            float4 b4 = *(const float4*)&Bs[kk][tx * 4];
            float a[4] = {a4.x, a4.y, a4.z, a4.w};
            float b[4] = {b4.x, b4.y, b4.z, b4.w};
            #pragma unroll
            for (int i = 0; i < 4; ++i)
                #pragma unroll
                for (int j = 0; j < 4; ++j)
                    acc[i][j] = fmaf(a[i], b[j], acc[i][j]);
        }
        __syncthreads();
    }

    #pragma unroll
    for (int i = 0; i < 4; ++i) {
        int m = m0 + ty * 4 + i;
        #pragma unroll
        for (int j = 0; j < 4; ++j) {
            int n = n0 + tx * 4 + j;
            C[(size_t)m * N + n] = acc[i][j] + bias[n];
        }
    }
}

// ---------------- persistent recurrence kernel -------------------------------
// 128 blocks, 256 threads. 4 phases per step separated by grid barriers.
__global__ __launch_bounds__(REC_THREADS)
void recurrence_kernel(const float* __restrict__ Whz,
                       const float* __restrict__ Whr,
                       const float* __restrict__ Whn) {
    __shared__ float As[16][68];
    __shared__ float Bs[16][68];

    const int bid = blockIdx.x;
    const int tid = threadIdx.x;
    const int row = tid >> 2;
    const int kq  = (tid & 3) * 4;
    const int ty  = tid >> 4;
    const int tx  = tid & 15;
    unsigned phase = 0;

    // phase A decomposition: 2 gates x 16 ntiles x KS_ZR
    const int tileA = bid & 31;
    const int gateA = tileA >> 4;
    const int n0A   = (tileA & 15) * 64;
    const int k0A   = (bid >> 5) * (DHID / KS_ZR);        // 256-wide chunk
    const float* WA0;  // set per-call below
    float* partA = g_pzr + ((size_t)(gateA * KS_ZR + (bid >> 5))) * BHD;

    // phase C decomposition: 16 ntiles x KS_N
    const int n0C = (bid & 15) * 64;
    const int k0C = (bid >> 4) * (DHID / KS_N);           // 128-wide chunk
    float* partC = g_pn + (size_t)(bid >> 4) * BHD;

    const float* WAsel = gateA ? Whr : Whz;

    for (int s = 0; s < SEQ; ++s) {
        // ---- phase A: z,r GEMM (A = g_h) ----
        {
            float acc[4][4] = {};
            for (int kt = 0; kt < DHID / KS_ZR; kt += 16) {
                int k = k0A + kt;
                float4 av = *(const float4*)&g_h[(size_t)row * DHID + k + kq];
                float4 wv = *(const float4*)&WAsel[(size_t)(n0A + row) * DHID + k + kq];
                As[kq + 0][row] = av.x; As[kq + 1][row] = av.y;
                As[kq + 2][row] = av.z; As[kq + 3][row] = av.w;
                Bs[kq + 0][row] = wv.x; Bs[kq + 1][row] = wv.y;
                Bs[kq + 2][row] = wv.z; Bs[kq + 3][row] = wv.w;
                __syncthreads();
                #pragma unroll
                for (int kk = 0; kk < 16; ++kk) {
                    float4 a4 = *(const float4*)&As[kk][ty * 4];
                    float4 b4 = *(const float4*)&Bs[kk][tx * 4];
                    float a[4] = {a4.x, a4.y, a4.z, a4.w};
                    float b[4] = {b4.x, b4.y, b4.z, b4.w};
                    #pragma unroll
                    for (int i = 0; i < 4; ++i)
                        #pragma unroll
                        for (int j = 0; j < 4; ++j)
                            acc[i][j] = fmaf(a[i], b[j], acc[i][j]);
                }
                __syncthreads();
            }
            #pragma unroll
            for (int i = 0; i < 4; ++i)
                #pragma unroll
                for (int j = 0; j < 4; ++j)
                    partA[(size_t)(ty * 4 + i) * DHID + n0A + tx * 4 + j] = acc[i][j];
        }
        gbar(phase);

        // ---- phase B: elementwise z, r*h ----
        for (int i = bid * REC_THREADS + tid; i < BHD; i += GRID_REC * REC_THREADS) {
            float tz = 0.f, tr = 0.f;
            #pragma unroll
            for (int ks = 0; ks < KS_ZR; ++ks) {
                tz += g_pzr[(size_t)ks * BHD + i];
                tr += g_pzr[(size_t)(KS_ZR + ks) * BHD + i];
            }
            float az = g_xz[(size_t)s * BHD + i] + tz;
            float ar = g_xr[(size_t)s * BHD + i] + tr;
            float z = 1.f / (1.f + __expf(-az));
            float r = 1.f / (1.f + __expf(-ar));
            g_z[i]  = z;
            g_rh[i] = r * g_h[i];
        }
        gbar(phase);

        // ---- phase C: n GEMM (A = g_rh) ----
        {
            float acc[4][4] = {};
            for (int kt = 0; kt < DHID / KS_N; kt += 16) {
                int k = k0C + kt;
                float4 av = *(const float4*)&g_rh[(size_t)row * DHID + k + kq];
                float4 wv = *(const float4*)&Whn[(size_t)(n0C + row) * DHID + k + kq];
                As[kq + 0][row] = av.x; As[kq + 1][row] = av.y;
                As[kq + 2][row] = av.z; As[kq + 3][row] = av.w;
                Bs[kq + 0][row] = wv.x; Bs[kq + 1][row] = wv.y;
                Bs[kq + 2][row] = wv.z; Bs[kq + 3][row] = wv.w;
                __syncthreads();
                #pragma unroll
                for (int kk = 0; kk < 16; ++kk) {
                    float4 a4 = *(const float4*)&As[kk][ty * 4];
                    float4 b4 = *(const float4*)&Bs[kk][tx * 4];
                    float a[4] = {a4.x, a4.y, a4.z, a4.w};
                    float b[4] = {b4.x, b4.y, b4.z, b4.w};
                    #pragma unroll
                    for (int i = 0; i < 4; ++i)
                        #pragma unroll
                        for (int j = 0; j < 4; ++j)
                            acc[i][j] = fmaf(a[i], b[j], acc[i][j]);
                }
                __syncthreads();
            }
            #pragma unroll
            for (int i = 0; i < 4; ++i)
                #pragma unroll
                for (int j = 0; j < 4; ++j)
                    partC[(size_t)(ty * 4 + i) * DHID + n0C + tx * 4 + j] = acc[i][j];
        }
        gbar(phase);

        // ---- phase D: elementwise n, h update ----
        for (int i = bid * REC_THREADS + tid; i < BHD; i += GRID_REC * REC_THREADS) {
            float tn = 0.f;
            #pragma unroll
            for (int ks = 0; ks < KS_N; ++ks)
                tn += g_pn[(size_t)ks * BHD + i];
            float an = g_xn[(size_t)s * BHD + i] + tn;
            float n  = tanhf(an);
            float z  = g_z[i];
            float h  = g_h[i];
            float hn = fmaf(z, n - h, h);   // (1-z)h + z n
            g_h[i] = hn;
            g_hs[(size_t)s * BHD + i] = hn;
        }
        gbar(phase);
    }
}

__global__ void copy_hlast_kernel(float* __restrict__ dst) {
    int i = blockIdx.x * 256 + threadIdx.x;
    dst[i] = g_h[i];
}

// ---------------- launch ----------------------------------------------------
extern "C" void kernel_launch(void* const* d_in, const int* in_sizes, int n_in,
                              void* d_out, int out_size) {
    const float* x   = (const float*)d_in[0];
    const float* h0  = (const float*)d_in[1];
    const float* Wxz = (const float*)d_in[2];
    const float* bxz = (const float*)d_in[3];
    const float* Whz = (const float*)d_in[4];
    const float* Wxr = (const float*)d_in[5];
    const float* bxr = (const float*)d_in[6];
    const float* Whr = (const float*)d_in[7];
    const float* Wxn = (const float*)d_in[8];
    const float* bxn = (const float*)d_in[9];
    const float* Whn = (const float*)d_in[10];
    const float* Why = (const float*)d_in[11];
    const float* bhy = (const float*)d_in[12];
    float* out = (float*)d_out;

    init_h_kernel<<<BHD / 256, 256>>>(h0);

    dim3 gpre(DHID / 64, (SEQ * BAT) / 64);   // (16, 512)
    sgemm_bias_kernel<<<gpre, 256>>>(x, 0, Wxz, bxz, nullptr, 0, SEQ * BAT, DHID, DIN);
    sgemm_bias_kernel<<<gpre, 256>>>(x, 0, Wxr, bxr, nullptr, 1, SEQ * BAT, DHID, DIN);
    sgemm_bias_kernel<<<gpre, 256>>>(x, 0, Wxn, bxn, nullptr, 2, SEQ * BAT, DHID, DIN);

    recurrence_kernel<<<GRID_REC, REC_THREADS>>>(Whz, Whr, Whn);

    sgemm_bias_kernel<<<gpre, 256>>>(nullptr, 1, Why, bhy, out, 3, SEQ * BAT, DOUT, DHID);
    copy_hlast_kernel<<<BHD / 256, 256>>>(out + (size_t)SEQ * BAT * DOUT);
}

// round 3
// speedup vs baseline: 1.4514x; 1.4514x over previous
#include <cuda_runtime.h>
#include <cuda_bf16.h>
#include <cstdint>

#define SEQ   512
#define BAT   64
#define DH    1024
#define KP    3072                 // tri-split K' = 3*1024
#define MROWS (SEQ*BAT)            // 32768
#define BHD   (BAT*DH)             // 65536

#define GRID_REC 128
#define REC_THREADS 256
#define KS_ZR 4
#define KS_N  8
#define WPSZ  ((size_t)DH*KP)
#define LDT   72                   // padded smem row stride (bf16 elems)

// ---------------- device globals (no allocations allowed) -------------------
__device__ __nv_bfloat16 g_xp [(size_t)MROWS*KP];   // x tri-split (hi,lo,hi)
__device__ __nv_bfloat16 g_hsp[(size_t)MROWS*KP];   // hs tri-split
__device__ __nv_bfloat16 g_wp [7*WPSZ];             // weights tri-split (hi,hi,lo)
__device__ float g_xz[(size_t)SEQ*BHD];
__device__ float g_xr[(size_t)SEQ*BHD];
__device__ float g_xn[(size_t)SEQ*BHD];
__device__ float g_h [BHD];
__device__ float g_z [BHD];
__device__ __nv_bfloat16 g_hp [BAT*KP];             // h tri-split
__device__ __nv_bfloat16 g_rhp[BAT*KP];             // r*h tri-split
__device__ float g_pzr[2*KS_ZR*(size_t)BHD];
__device__ float g_pn [KS_N*(size_t)BHD];
__device__ unsigned g_barcnt;
__device__ volatile unsigned g_barsense;

// ---------------- helpers ----------------------------------------------------
__device__ __forceinline__ void trisplit(float v, __nv_bfloat16& hi, __nv_bfloat16& lo) {
    hi = __float2bfloat16(v);
    lo = __float2bfloat16(v - __bfloat162float(hi));
}

__device__ __forceinline__ uint32_t smem_u32(const void* p) {
    return (uint32_t)__cvta_generic_to_shared(p);
}

__device__ __forceinline__ void ldsm_x4(uint32_t* r, uint32_t addr) {
    asm volatile("ldmatrix.sync.aligned.m8n8.x4.shared.b16 {%0,%1,%2,%3}, [%4];"
                 : "=r"(r[0]), "=r"(r[1]), "=r"(r[2]), "=r"(r[3]) : "r"(addr));
}

__device__ __forceinline__ void mma_bf16(float* d, const uint32_t* a,
                                         uint32_t b0, uint32_t b1) {
    asm volatile("mma.sync.aligned.m16n8k16.row.col.f32.bf16.bf16.f32 "
                 "{%0,%1,%2,%3},{%4,%5,%6,%7},{%8,%9},{%0,%1,%2,%3};"
                 : "+f"(d[0]), "+f"(d[1]), "+f"(d[2]), "+f"(d[3])
                 : "r"(a[0]), "r"(a[1]), "r"(a[2]), "r"(a[3]), "r"(b0), "r"(b1));
}

// ---------------- conversion kernels ----------------------------------------
__global__ void conv_a_kernel(const float* __restrict__ x) {
    size_t i = (size_t)blockIdx.x * 256 + threadIdx.x;   // < MROWS*DH
    float v = x[i];
    size_t m = i >> 10, k = i & 1023;
    __nv_bfloat16 hi, lo; trisplit(v, hi, lo);
    __nv_bfloat16* dst = g_xp + m * KP;
    dst[k] = hi; dst[1024 + k] = lo; dst[2048 + k] = hi;
}

__global__ void conv_w_kernel(const float* w0, const float* w1, const float* w2,
                              const float* w3, const float* w4, const float* w5,
                              const float* w6) {
    int z = blockIdx.z;
    const float* src = (z==0)?w0:(z==1)?w1:(z==2)?w2:(z==3)?w3:(z==4)?w4:(z==5)?w5:w6;
    size_t i = (size_t)blockIdx.x * 256 + threadIdx.x;   // < DH*DH
    float v = src[i];
    size_t row = i >> 10, k = i & 1023;
    __nv_bfloat16 hi, lo; trisplit(v, hi, lo);
    __nv_bfloat16* dst = g_wp + (size_t)z * WPSZ + row * KP;
    dst[k] = hi; dst[1024 + k] = hi; dst[2048 + k] = lo;
}

// ---------------- init -------------------------------------------------------
__global__ void init_h_kernel(const float* __restrict__ h0) {
    int i = blockIdx.x * 256 + threadIdx.x;
    float v = h0[i];
    g_h[i] = v;
    int b = i >> 10, k = i & 1023;
    __nv_bfloat16 hi, lo; trisplit(v, hi, lo);
    __nv_bfloat16* dst = g_hp + (size_t)b * KP;
    dst[k] = hi; dst[1024 + k] = lo; dst[2048 + k] = hi;
    if (i == 0) { g_barcnt = 0; g_barsense = 0; }
}

// ---------------- grid barrier ----------------------------------------------
__device__ __forceinline__ void gbar(unsigned& phase) {
    phase++;
    __threadfence();
    __syncthreads();
    if (threadIdx.x == 0) {
        unsigned a = atomicAdd(&g_barcnt, 1);
        if (a == GRID_REC - 1) {
            g_barcnt = 0;
            __threadfence();
            g_barsense = phase;
        } else {
            while (g_barsense != phase) { __nanosleep(32); }
        }
    }
    __syncthreads();
    __threadfence();
}

// ---------------- big bf16 GEMM: C[M,1024] = A'[M,KP] . W'[1024,KP]^T + bias -
// BM=128, BN=64, BK=64, 256 threads, 8 warps (4m x 2n), warp tile 32x32.
__global__ __launch_bounds__(256)
void gemm_bf16p(int a_sel, int w_base, int c_mode,
                const float* __restrict__ bias0, const float* __restrict__ bias1,
                const float* __restrict__ bias2, float* __restrict__ Cext) {
    const int z = blockIdx.z;
    const __nv_bfloat16* A = a_sel ? g_hsp : g_xp;
    const __nv_bfloat16* W = g_wp + (size_t)(w_base + z) * WPSZ;
    const float* bias = (z == 0) ? bias0 : (z == 1) ? bias1 : bias2;
    float* C = (c_mode == 1) ? Cext : (z == 0 ? g_xz : z == 1 ? g_xr : g_xn);

    __shared__ __nv_bfloat16 As[128 * LDT];
    __shared__ __nv_bfloat16 Bs[64 * LDT];

    const int m0 = blockIdx.y * 128, n0 = blockIdx.x * 64;
    const int t = threadIdx.x, lane = t & 31, w8 = t >> 5;
    const int wm = w8 >> 1, wn = w8 & 1;
    const int lr = t >> 3, lq = t & 7;

    float acc[2][4][4] = {};

    for (int k0 = 0; k0 < KP; k0 += 64) {
        #pragma unroll
        for (int p = 0; p < 4; ++p) {
            int r = lr + p * 32;
            ((uint4*)(As + r * LDT))[lq] =
                *((const uint4*)(A + (size_t)(m0 + r) * KP + k0) + lq);
        }
        #pragma unroll
        for (int p = 0; p < 2; ++p) {
            int r = lr + p * 32;
            ((uint4*)(Bs + r * LDT))[lq] =
                *((const uint4*)(W + (size_t)(n0 + r) * KP + k0) + lq);
        }
        __syncthreads();
        #pragma unroll
        for (int kk = 0; kk < 4; ++kk) {
            const int ks = kk * 16;
            uint32_t aF[2][4], bF[2][4];
            #pragma unroll
            for (int mi = 0; mi < 2; ++mi) {
                int arow = wm * 32 + mi * 16 + (lane & 15);
                int acol = ks + ((lane >> 4) << 3);
                ldsm_x4(aF[mi], smem_u32(As + arow * LDT + acol));
            }
            #pragma unroll
            for (int nq = 0; nq < 2; ++nq) {
                int brow = wn * 32 + nq * 16 + (lane & 7) + (((lane >> 4) & 1) << 3);
                int bcol = ks + (((lane >> 3) & 1) << 3);
                ldsm_x4(bF[nq], smem_u32(Bs + brow * LDT + bcol));
            }
            #pragma unroll
            for (int mi = 0; mi < 2; ++mi)
                #pragma unroll
                for (int nq = 0; nq < 2; ++nq) {
                    mma_bf16(acc[mi][2 * nq],     aF[mi], bF[nq][0], bF[nq][1]);
                    mma_bf16(acc[mi][2 * nq + 1], aF[mi], bF[nq][2], bF[nq][3]);
                }
        }
        __syncthreads();
    }

    #pragma unroll
    for (int mi = 0; mi < 2; ++mi)
        #pragma unroll
        for (int ni = 0; ni < 4; ++ni) {
            int row = m0 + wm * 32 + mi * 16 + (lane >> 2);
            int col = n0 + wn * 32 + ni * 8 + (lane & 3) * 2;
            float b0 = bias[col], b1 = bias[col + 1];
            float* a = acc[mi][ni];
            *(float2*)&C[(size_t)row * DH + col]       = make_float2(a[0] + b0, a[1] + b1);
            *(float2*)&C[(size_t)(row + 8) * DH + col] = make_float2(a[2] + b0, a[3] + b1);
        }
}

// ---------------- recurrence 64x64 MMA tile over a K chunk -------------------
// 8 warps (2m x 4n), warp tile 32x16. Writes 64x64 fp32 partial (no bias).
__device__ __forceinline__ void mma_block64(
    const __nv_bfloat16* __restrict__ Ag,   // 64 rows, pitch KP
    const __nv_bfloat16* __restrict__ Wg,   // weight base, pitch KP
    int n0, int k0, int klen,
    float* __restrict__ part,               // BHD layout [b][n]
    __nv_bfloat16* As, __nv_bfloat16* Bs) {
    const int t = threadIdx.x, lane = t & 31, w8 = t >> 5;
    const int wm = w8 >> 2, wn = w8 & 3;
    const int lr = t >> 3, lq = t & 7;

    float acc[2][2][4] = {};

    for (int kt = 0; kt < klen; kt += 64) {
        const int k = k0 + kt;
        #pragma unroll
        for (int p = 0; p < 2; ++p) {
            int r = lr + p * 32;
            ((uint4*)(As + r * LDT))[lq] =
                *((const uint4*)(Ag + (size_t)r * KP + k) + lq);
            ((uint4*)(Bs + r * LDT))[lq] =
                *((const uint4*)(Wg + (size_t)(n0 + r) * KP + k) + lq);
        }
        __syncthreads();
        #pragma unroll
        for (int kk = 0; kk < 4; ++kk) {
            const int ks = kk * 16;
            uint32_t aF[2][4], bF[4];
            #pragma unroll
            for (int mi = 0; mi < 2; ++mi) {
                int arow = wm * 32 + mi * 16 + (lane & 15);
                int acol = ks + ((lane >> 4) << 3);
                ldsm_x4(aF[mi], smem_u32(As + arow * LDT + acol));
            }
            {
                int brow = wn * 16 + (lane & 7) + (((lane >> 4) & 1) << 3);
                int bcol = ks + (((lane >> 3) & 1) << 3);
                ldsm_x4(bF, smem_u32(Bs + brow * LDT + bcol));
            }
            #pragma unroll
            for (int mi = 0; mi < 2; ++mi) {
                mma_bf16(acc[mi][0], aF[mi], bF[0], bF[1]);
                mma_bf16(acc[mi][1], aF[mi], bF[2], bF[3]);
            }
        }
        __syncthreads();
    }

    #pragma unroll
    for (int mi = 0; mi < 2; ++mi)
        #pragma unroll
        for (int ni = 0; ni < 2; ++ni) {
            int row = wm * 32 + mi * 16 + (lane >> 2);        // batch
            int col = n0 + wn * 16 + ni * 8 + (lane & 3) * 2;
            float* a = acc[mi][ni];
            *(float2*)&part[(size_t)row * DH + col]       = make_float2(a[0], a[1]);
            *(float2*)&part[(size_t)(row + 8) * DH + col] = make_float2(a[2], a[3]);
        }
}

// ---------------- persistent recurrence -------------------------------------
__global__ __launch_bounds__(REC_THREADS)
void recurrence_kernel() {
    __shared__ __nv_bfloat16 As[64 * LDT];
    __shared__ __nv_bfloat16 Bs[64 * LDT];

    const int bid = blockIdx.x;
    const int tid = threadIdx.x;
    unsigned phase = 0;

    // phase A decomposition: gate(2) x ntile(16) x ks(KS_ZR)
    const int gateA = bid >> 6;
    const int subA  = bid & 63;
    const int ksA   = subA >> 4;
    const int n0A   = (subA & 15) * 64;
    const int k0A   = ksA * (KP / KS_ZR);               // 768-wide
    const __nv_bfloat16* WA = g_wp + (size_t)(3 + gateA) * WPSZ;
    float* partA = g_pzr + ((size_t)(gateA * KS_ZR + ksA)) * BHD;

    // phase C decomposition: ntile(16) x ks(KS_N)
    const int n0C = (bid & 15) * 64;
    const int ksC = bid >> 4;
    const int k0C = ksC * (KP / KS_N);                  // 384-wide
    const __nv_bfloat16* WC = g_wp + (size_t)5 * WPSZ;
    float* partC = g_pn + (size_t)ksC * BHD;

    for (int s = 0; s < SEQ; ++s) {
        // ---- phase A: z,r partial GEMMs (A = g_hp) ----
        mma_block64(g_hp, WA, n0A, k0A, KP / KS_ZR, partA, As, Bs);
        gbar(phase);

        // ---- phase B: reduce + sigmoid + rh tri-split ----
        for (int i = bid * REC_THREADS + tid; i < BHD; i += GRID_REC * REC_THREADS) {
            float tz = 0.f, tr = 0.f;
            #pragma unroll
            for (int ks = 0; ks < KS_ZR; ++ks) {
                tz += g_pzr[(size_t)ks * BHD + i];
                tr += g_pzr[(size_t)(KS_ZR + ks) * BHD + i];
            }
            float az = g_xz[(size_t)s * BHD + i] + tz;
            float ar = g_xr[(size_t)s * BHD + i] + tr;
            float zv = 1.f / (1.f + __expf(-az));
            float rv = 1.f / (1.f + __expf(-ar));
            g_z[i] = zv;
            float rh = rv * g_h[i];
            int b = i >> 10, k = i & 1023;
            __nv_bfloat16 hi, lo; trisplit(rh, hi, lo);
            __nv_bfloat16* dst = g_rhp + (size_t)b * KP;
            dst[k] = hi; dst[1024 + k] = lo; dst[2048 + k] = hi;
        }
        gbar(phase);

        // ---- phase C: n partial GEMM (A = g_rhp) ----
        mma_block64(g_rhp, WC, n0C, k0C, KP / KS_N, partC, As, Bs);
        gbar(phase);

        // ---- phase D: reduce + tanh + h update ----
        for (int i = bid * REC_THREADS + tid; i < BHD; i += GRID_REC * REC_THREADS) {
            float tn = 0.f;
            #pragma unroll
            for (int ks = 0; ks < KS_N; ++ks)
                tn += g_pn[(size_t)ks * BHD + i];
            float an = g_xn[(size_t)s * BHD + i] + tn;
            float nv = tanhf(an);
            float zv = g_z[i];
            float h  = g_h[i];
            float hn = fmaf(zv, nv - h, h);
            g_h[i] = hn;
            int b = i >> 10, k = i & 1023;
            __nv_bfloat16 hi, lo; trisplit(hn, hi, lo);
            __nv_bfloat16* dh = g_hp + (size_t)b * KP;
            dh[k] = hi; dh[1024 + k] = lo; dh[2048 + k] = hi;
            __nv_bfloat16* ds = g_hsp + ((size_t)s * BAT + b) * KP;
            ds[k] = hi; ds[1024 + k] = lo; ds[2048 + k] = hi;
        }
        gbar(phase);
    }
}

__global__ void copy_hlast_kernel(float* __restrict__ dst) {
    int i = blockIdx.x * 256 + threadIdx.x;
    dst[i] = g_h[i];
}

// ---------------- launch ----------------------------------------------------
extern "C" void kernel_launch(void* const* d_in, const int* in_sizes, int n_in,
                              void* d_out, int out_size) {
    const float* x   = (const float*)d_in[0];
    const float* h0  = (const float*)d_in[1];
    const float* Wxz = (const float*)d_in[2];
    const float* bxz = (const float*)d_in[3];
    const float* Whz = (const float*)d_in[4];
    const float* Wxr = (const float*)d_in[5];
    const float* bxr = (const float*)d_in[6];
    const float* Whr = (const float*)d_in[7];
    const float* Wxn = (const float*)d_in[8];
    const float* bxn = (const float*)d_in[9];
    const float* Whn = (const float*)d_in[10];
    const float* Why = (const float*)d_in[11];
    const float* bhy = (const float*)d_in[12];
    float* out = (float*)d_out;

    // conversions: weights (order: Wxz,Wxr,Wxn,Whz,Whr,Whn,Why), then x
    conv_w_kernel<<<dim3(DH * DH / 256, 1, 7), 256>>>(Wxz, Wxr, Wxn, Whz, Whr, Whn, Why);
    conv_a_kernel<<<(size_t)MROWS * DH / 256, 256>>>(x);
    init_h_kernel<<<BHD / 256, 256>>>(h0);

    // pre-projections: xz, xr, xn in one launch (grid.z = gate)
    gemm_bf16p<<<dim3(DH / 64, MROWS / 128, 3), 256>>>(
        0, 0, 0, bxz, bxr, bxn, nullptr);

    // recurrence (persistent, 4 grid barriers per step)
    recurrence_kernel<<<GRID_REC, REC_THREADS>>>();

    // output GEMM: out = hs' . Why'^T + bhy
    gemm_bf16p<<<dim3(DH / 64, MROWS / 128, 1), 256>>>(
        1, 6, 1, bhy, bhy, bhy, out);

    copy_hlast_kernel<<<BHD / 256, 256>>>(out + (size_t)MROWS * DH);
}